// round 2
// baseline (speedup 1.0000x reference)
#include <cuda_runtime.h>

// CausalConv1d: y[b,l,d] = bias[d] + sum_{k=0..3} x[b, l-3+k, d] * w[d,0,k]
// x: (B=8, L=4096, D=1024) fp32, contiguous D innermost.
// w: (D, 1, K=4) fp32. b: (D,) fp32. Output (B, L, D) fp32.
//
// HBM-bound: read x once (+9% halo), write y once. float4 over D,
// sliding register window over L.

#define CC_B 8
#define CC_L 4096
#define CC_D 1024
#define CC_K 4
#define CC_LC 32                 // L-chunk per thread
#define CC_DV (CC_D / 4)         // float4 lanes over D = 256
#define CC_NCHUNK (CC_L / CC_LC) // 128

__global__ __launch_bounds__(CC_DV, 4)
void causal_conv1d_kernel(const float4* __restrict__ x,
                          const float*  __restrict__ w,
                          const float4* __restrict__ bias,
                          float4*       __restrict__ y)
{
    const int d4    = threadIdx.x;            // 0..255 (float4 index over D)
    const int blk   = blockIdx.x;             // b * NCHUNK + chunk
    const int chunk = blk & (CC_NCHUNK - 1);
    const int b     = blk >> 7;               // blk / 128
    const int d0    = d4 * 4;

    // Per-lane weights: 4 channels x 4 taps. w layout: w[d*K + k].
    float w0x = w[(d0 + 0) * CC_K + 0], w1x = w[(d0 + 0) * CC_K + 1],
          w2x = w[(d0 + 0) * CC_K + 2], w3x = w[(d0 + 0) * CC_K + 3];
    float w0y = w[(d0 + 1) * CC_K + 0], w1y = w[(d0 + 1) * CC_K + 1],
          w2y = w[(d0 + 1) * CC_K + 2], w3y = w[(d0 + 1) * CC_K + 3];
    float w0z = w[(d0 + 2) * CC_K + 0], w1z = w[(d0 + 2) * CC_K + 1],
          w2z = w[(d0 + 2) * CC_K + 2], w3z = w[(d0 + 2) * CC_K + 3];
    float w0w = w[(d0 + 3) * CC_K + 0], w1w = w[(d0 + 3) * CC_K + 1],
          w2w = w[(d0 + 3) * CC_K + 2], w3w = w[(d0 + 3) * CC_K + 3];

    const float4 bv = bias[d4];

    const int l0 = chunk * CC_LC;
    const size_t rowbase = (size_t)b * CC_L * CC_DV + d4;  // + l*CC_DV per row

    // Sliding window: x at l0-3, l0-2, l0-1 (zero for l<0; only chunk 0 hits pad).
    float4 xm3, xm2, xm1;
    if (l0 == 0) {
        xm3 = make_float4(0.f, 0.f, 0.f, 0.f);
        xm2 = xm3;
        xm1 = xm3;
    } else {
        xm3 = x[rowbase + (size_t)(l0 - 3) * CC_DV];
        xm2 = x[rowbase + (size_t)(l0 - 2) * CC_DV];
        xm1 = x[rowbase + (size_t)(l0 - 1) * CC_DV];
    }

    #pragma unroll 8
    for (int i = 0; i < CC_LC; i++) {
        const size_t off = rowbase + (size_t)(l0 + i) * CC_DV;
        const float4 xc = x[off];
        float4 r;
        r.x = fmaf(w0x, xm3.x, fmaf(w1x, xm2.x, fmaf(w2x, xm1.x, fmaf(w3x, xc.x, bv.x))));
        r.y = fmaf(w0y, xm3.y, fmaf(w1y, xm2.y, fmaf(w2y, xm1.y, fmaf(w3y, xc.y, bv.y))));
        r.z = fmaf(w0z, xm3.z, fmaf(w1z, xm2.z, fmaf(w2z, xm1.z, fmaf(w3z, xc.z, bv.z))));
        r.w = fmaf(w0w, xm3.w, fmaf(w1w, xm2.w, fmaf(w2w, xm1.w, fmaf(w3w, xc.w, bv.w))));
        y[off] = r;
        xm3 = xm2;
        xm2 = xm1;
        xm1 = xc;
    }
}

extern "C" void kernel_launch(void* const* d_in, const int* in_sizes, int n_in,
                              void* d_out, int out_size)
{
    (void)in_sizes; (void)n_in; (void)out_size;
    const float4* x    = (const float4*)d_in[0];
    const float*  w    = (const float*)d_in[1];
    const float4* bias = (const float4*)d_in[2];
    float4*       y    = (float4*)d_out;

    dim3 grid(CC_B * CC_NCHUNK);   // 1024 blocks
    dim3 block(CC_DV);             // 256 threads
    causal_conv1d_kernel<<<grid, block>>>(x, w, bias, y);
}